// round 1
// baseline (speedup 1.0000x reference)
#include <cuda_runtime.h>

#define Bb     1024
#define ITEMS  55
#define NSTR   (Bb*ITEMS)    /* 56320 */
#define TT     80
#define HH     16
#define OUTD   24
#define EOS_TOK 129

#define OFF_CLSEMB 24576          /* 1024*24 */
#define OFF_STREMB 925696         /* 24576 + 1024*55*16 */

/* ---- scratch (device globals; no allocations allowed) ---- */
__device__ float g_tab[2*128*16*4];   /* gi tables (bih folded), [dir][char][unit][r,z,n,pad] */
__device__ float g_ctab[19*16];       /* class-branch gi table (bih folded) */
__device__ float g_hbuf[2*NSTR*HH];   /* GRU final hiddens, [dir][n][16] */
__device__ float g_hcls[Bb*HH];       /* class RNN final hiddens */
__device__ unsigned char g_len[NSTR]; /* string lengths (0..80) */

__constant__ int c_map[19] = {128,93,41,91,61,34,40,37,33,63,43,47,36,42,96,48,95,46,128};

__device__ __forceinline__ float fsig(float x) {
    float e = __expf(-x);
    return __fdividef(1.f, 1.f + e);
}
__device__ __forceinline__ float ftanh_(float x) {
    /* tanh(x) = 2*sigmoid(2x) - 1 : safe at extremes, 1 EX2 + 1 RCP */
    float e = __expf(-2.f * x);
    return __fdividef(2.f, 1.f + e) - 1.f;
}

/* ================= K0: precompute gi tables ================= */
__global__ void k_tables(const float* __restrict__ emb,
                         const float* __restrict__ Wf, const float* __restrict__ bf,
                         const float* __restrict__ Wb, const float* __restrict__ bb,
                         const float* __restrict__ rW, const float* __restrict__ rb)
{
    int idx = blockIdx.x * blockDim.x + threadIdx.x;
    if (idx < 2*128*16) {
        int dir = idx >> 11;
        int c   = (idx >> 4) & 127;
        int j   = idx & 15;
        const float* W  = dir ? Wb : Wf;
        const float* bi = dir ? bb : bf;
        float e[16];
        #pragma unroll
        for (int d = 0; d < 16; d++) e[d] = (c == 0) ? 0.f : emb[c*16 + d];  /* padding_idx=0 */
        float* o = &g_tab[idx*4];
        #pragma unroll
        for (int g = 0; g < 3; g++) {
            float v = bi[g*16 + j];
            #pragma unroll
            for (int d = 0; d < 16; d++) v += e[d] * W[(g*16 + j)*16 + d];
            o[g] = v;
        }
        o[3] = 0.f;
    } else if (idx < 2*128*16 + 19*16) {
        int t = idx - 2*128*16;
        int cls = t >> 4, j = t & 15;
        int c = c_map[cls];   /* never 0 */
        float v = rb[j];
        #pragma unroll
        for (int d = 0; d < 16; d++) v += emb[c*16 + d] * rW[j*16 + d];
        g_ctab[t] = v;
    }
}

/* ================= K1: inv_class_emb output ================= */
__global__ void __launch_bounds__(256) k_clsemb(const int* __restrict__ ocl,
                                                const float* __restrict__ emb,
                                                float* __restrict__ out /* d_out + OFF_CLSEMB */)
{
    int q = blockIdx.x * blockDim.x + threadIdx.x;   /* 0 .. NSTR*4 */
    if (q >= NSTR*4) return;
    int item = q >> 2, d4 = q & 3;
    int c = c_map[ocl[item]];    /* never row 0 */
    const float4* e4 = (const float4*)emb;
    ((float4*)out)[q] = e4[c*4 + d4];
}

/* ================= K2: str_emb output + lengths ================= */
__global__ void __launch_bounds__(256) k_stremb(const int* __restrict__ strs,
                                                const float* __restrict__ emb,
                                                float* __restrict__ out /* d_out + OFF_STREMB */)
{
    __shared__ float4 semb[130*4];
    __shared__ unsigned char sch[8][80];
    int tid = threadIdx.x;
    const float4* e4 = (const float4*)emb;
    for (int i = tid; i < 520; i += 256) {
        float4 v = e4[i];
        if (i < 4) v = make_float4(0.f, 0.f, 0.f, 0.f);   /* emb row 0 zeroed */
        semb[i] = v;
    }
    int w = tid >> 5, lane = tid & 31;
    int n = blockIdx.x * 8 + w;
    const int* sp = strs + (size_t)n * 80;
    int c0 = sp[lane];
    int c1 = sp[32 + lane];
    int c2 = (lane < 16) ? sp[64 + lane] : 0;
    unsigned m0 = __ballot_sync(0xffffffffu, c0 != 0);
    unsigned m1 = __ballot_sync(0xffffffffu, c1 != 0);
    unsigned m2 = __ballot_sync(0xffffffffu, (lane < 16) && (c2 != 0));
    int len = __popc(m0) + __popc(m1) + __popc(m2);
    sch[w][lane]      = (unsigned char)c0;
    sch[w][32 + lane] = (unsigned char)c1;
    if (lane < 16) sch[w][64 + lane] = (unsigned char)c2;
    if (lane == 0) g_len[n] = (unsigned char)len;
    __syncthreads();
    float4* o4 = (float4*)out + (size_t)n * 320;
    #pragma unroll
    for (int it = 0; it < 10; it++) {
        int flat = it*32 + lane;
        int t = flat >> 2, d4 = flat & 3;
        int c = (t == len) ? EOS_TOK : (int)sch[w][t];
        o4[flat] = semb[c*4 + d4];
    }
}

/* ================= K3: bidirectional GRU (the heavy kernel) =================
   16 threads per sequence; thread j owns hidden unit j. 512 thr = 32 seqs/block.
   grid = (1760, 2): blockIdx.y = direction. */
__global__ void __launch_bounds__(512) k_gru(const int* __restrict__ strs,
                                             const float* __restrict__ Whf, const float* __restrict__ bhf,
                                             const float* __restrict__ Whb, const float* __restrict__ bhb)
{
    __shared__ float4 stab[128*16];        /* gi table for this dir: [char][unit] = (r,z,n,_) */
    __shared__ unsigned char sch[32*80];
    int tid = threadIdx.x;
    int dir = blockIdx.y;

    const float4* gt = (const float4*)g_tab + dir*2048;
    for (int i = tid; i < 2048; i += 512) stab[i] = gt[i];

    int base = blockIdx.x * 32;
    const int* sp = strs + (size_t)base * 80;
    for (int i = tid; i < 2560; i += 512) sch[i] = (unsigned char)sp[i];

    const float* Whh = dir ? Whb : Whf;
    const float* bhh = dir ? bhb : bhf;
    int j = tid & 15;
    float wr[16], wz[16], wn[16];
    const float4* W4 = (const float4*)Whh;
    #pragma unroll
    for (int kk = 0; kk < 4; kk++) {
        float4 a = W4[j*4 + kk];
        wr[kk*4+0]=a.x; wr[kk*4+1]=a.y; wr[kk*4+2]=a.z; wr[kk*4+3]=a.w;
        float4 b = W4[(16+j)*4 + kk];
        wz[kk*4+0]=b.x; wz[kk*4+1]=b.y; wz[kk*4+2]=b.z; wz[kk*4+3]=b.w;
        float4 c = W4[(32+j)*4 + kk];
        wn[kk*4+0]=c.x; wn[kk*4+1]=c.y; wn[kk*4+2]=c.z; wn[kk*4+3]=c.w;
    }
    float bhr = bhh[j], bhz = bhh[16 + j], bhn = bhh[32 + j];
    __syncthreads();

    int s = tid >> 4;
    unsigned gmask = (tid & 16) ? 0xFFFF0000u : 0x0000FFFFu;
    const unsigned char* ch = &sch[s * 80];

    int cnt = 0;
    #pragma unroll
    for (int i = 0; i < 5; i++) cnt += (ch[j + 16*i] != 0);
    #pragma unroll
    for (int o = 8; o; o >>= 1) cnt += __shfl_xor_sync(gmask, cnt, o, 16);
    int len = cnt;

    float h = 0.f;
    for (int t = 0; t < len; t++) {
        int pos = dir ? (len - 1 - t) : t;
        int c = ch[pos];
        float4 gi = stab[c*16 + j];
        float sr = gi.x + bhr;
        float sz = gi.y + bhz;
        float hn = bhn;
        #pragma unroll
        for (int k = 0; k < 16; k++) {
            float hk = __shfl_sync(gmask, h, k, 16);
            sr += wr[k]*hk;
            sz += wz[k]*hk;
            hn += wn[k]*hk;
        }
        float r = fsig(sr);
        float z = fsig(sz);
        float nn = ftanh_(gi.z + r*hn);
        h = nn + z*(h - nn);
    }
    g_hbuf[((size_t)dir*NSTR + base + s)*16 + j] = h;
}

/* ================= K4: class-branch vanilla RNN ================= */
__global__ void __launch_bounds__(512) k_cls(const int* __restrict__ ocl,
                                             const float* __restrict__ Whh,
                                             const float* __restrict__ bhh)
{
    __shared__ float sct[19*16];
    __shared__ unsigned char soc[32*55];
    int tid = threadIdx.x;
    if (tid < 304) sct[tid] = g_ctab[tid];
    int base = blockIdx.x * 32;
    for (int i = tid; i < 1760; i += 512) soc[i] = (unsigned char)ocl[base*55 + i];

    int j = tid & 15;
    float w[16];
    const float4* W4 = (const float4*)Whh;
    #pragma unroll
    for (int kk = 0; kk < 4; kk++) {
        float4 a = W4[j*4 + kk];
        w[kk*4+0]=a.x; w[kk*4+1]=a.y; w[kk*4+2]=a.z; w[kk*4+3]=a.w;
    }
    float bh = bhh[j];
    __syncthreads();

    int s = tid >> 4;
    unsigned gmask = (tid & 16) ? 0xFFFF0000u : 0x0000FFFFu;
    const unsigned char* oc = &soc[s * 55];
    int cnt = 0;
    #pragma unroll
    for (int i = 0; i < 4; i++) { int p = j + 16*i; cnt += (p < 55) ? (oc[p] != 18) : 0; }
    #pragma unroll
    for (int o = 8; o; o >>= 1) cnt += __shfl_xor_sync(gmask, cnt, o, 16);
    int len = cnt;

    float h = 0.f;
    for (int t = 0; t < len; t++) {
        int c = oc[t];
        float acc = sct[c*16 + j] + bh;
        #pragma unroll
        for (int k = 0; k < 16; k++) {
            float hk = __shfl_sync(gmask, h, k, 16);
            acc += w[k]*hk;
        }
        h = ftanh_(acc);
    }
    g_hcls[(base + s)*16 + j] = h;
}

/* ================= K5: pooling + fusion MLP -> inv_features ================= */
__global__ void __launch_bounds__(256) k_fuse(const float* __restrict__ W1, const float* __restrict__ b1,
                                              const float* __restrict__ W2, const float* __restrict__ b2,
                                              float* __restrict__ out)
{
    __shared__ float comb[8][48];
    __shared__ float h1s[8][16];
    int w = threadIdx.x >> 5, lane = threadIdx.x & 31;
    int b = blockIdx.x * 8 + w;
    const float* hf = &g_hbuf[0];
    const float* hb = &g_hbuf[(size_t)NSTR * 16];
    float pooled = 0.f, cnt = 0.f;
    int nb = b * ITEMS;
    for (int i = 0; i < ITEMS; i++) {
        int n = nb + i;
        if (g_len[n]) {   /* str_mask: sum(chars)>0 <=> any nonzero char */
            cnt += 1.f;
            float hv = (lane < 16) ? hf[n*16 + lane] : hb[n*16 + (lane - 16)];
            pooled += hv;
        }
    }
    pooled = pooled / (cnt + 1e-8f);
    if (lane < 16) comb[w][lane] = g_hcls[b*16 + lane];
    comb[w][16 + lane] = pooled;
    __syncwarp();
    if (lane < 16) {
        float a = b1[lane];
        #pragma unroll
        for (int k = 0; k < 48; k++) a += W1[lane*48 + k] * comb[w][k];
        h1s[w][lane] = fmaxf(a, 0.f);
    }
    __syncwarp();
    if (lane < 24) {
        float o = b2[lane];
        #pragma unroll
        for (int k = 0; k < 16; k++) o += W2[lane*16 + k] * h1s[w][k];
        out[b*24 + lane] = o;
    }
}

extern "C" void kernel_launch(void* const* d_in, const int* in_sizes, int n_in,
                              void* d_out, int out_size)
{
    const int*   ocl  = (const int*)d_in[0];
    const int*   strs = (const int*)d_in[1];
    const float* emb  = (const float*)d_in[2];
    const float* rW   = (const float*)d_in[3];
    const float* rWhh = (const float*)d_in[4];
    const float* rbih = (const float*)d_in[5];
    const float* rbhh = (const float*)d_in[6];
    const float* gWf  = (const float*)d_in[7];
    const float* gWhf = (const float*)d_in[8];
    const float* gbif = (const float*)d_in[9];
    const float* gbhf = (const float*)d_in[10];
    const float* gWb  = (const float*)d_in[11];
    const float* gWhb = (const float*)d_in[12];
    const float* gbib = (const float*)d_in[13];
    const float* gbhb = (const float*)d_in[14];
    const float* W1   = (const float*)d_in[15];
    const float* b1   = (const float*)d_in[16];
    const float* W2   = (const float*)d_in[17];
    const float* b2   = (const float*)d_in[18];
    float* out = (float*)d_out;

    k_tables<<<18, 256>>>(emb, gWf, gbif, gWb, gbib, rW, rbih);
    k_clsemb<<<880, 256>>>(ocl, emb, out + OFF_CLSEMB);
    k_stremb<<<7040, 256>>>(strs, emb, out + OFF_STREMB);
    dim3 gg(1760, 2);
    k_gru<<<gg, 512>>>(strs, gWhf, gbhf, gWhb, gbhb);
    k_cls<<<32, 512>>>(ocl, rWhh, rbhh);
    k_fuse<<<128, 256>>>(W1, b1, W2, b2, out);
}

// round 2
// speedup vs baseline: 1.3024x; 1.3024x over previous
#include <cuda_runtime.h>

typedef unsigned long long ull;

#define Bb     1024
#define ITEMS  55
#define NSTR   (Bb*ITEMS)    /* 56320 */
#define EOS_TOK 129

#define OFF_CLSEMB 24576          /* 1024*24 */
#define OFF_STREMB 925696         /* 24576 + 1024*55*16 */

/* ---- scratch (device globals; no allocations allowed) ---- */
__device__ ull   g_tr[2*128*8];       /* gi_r + bih_r + bhh_r, packed unit pairs */
__device__ ull   g_tz[2*128*8];       /* gi_z + bih_z + bhh_z */
__device__ ull   g_tn[2*128*8];       /* gi_n + bih_n (bhh_n NOT folded) */
__device__ float g_ctab[19*16];       /* class-branch gi table (bih folded) */
__device__ float g_hbuf[2*NSTR*16];   /* GRU final hiddens, [dir][n][16] */
__device__ float g_hcls[Bb*16];       /* class RNN final hiddens */
__device__ unsigned char g_len[NSTR]; /* string lengths (0..80) */

__constant__ int c_map[19] = {128,93,41,91,61,34,40,37,33,63,43,47,36,42,96,48,95,46,128};

__device__ __forceinline__ float fsig(float x) {
    float e = __expf(-x);
    return __fdividef(1.f, 1.f + e);
}
__device__ __forceinline__ float ftanh_(float x) {
    float e = __expf(-2.f * x);
    return __fdividef(2.f, 1.f + e) - 1.f;
}
__device__ __forceinline__ ull pack2(float x, float y) {
    ull r; asm("mov.b64 %0, {%1, %2};" : "=l"(r) : "f"(x), "f"(y)); return r;
}
__device__ __forceinline__ ull dup2(float x) {
    ull r; asm("mov.b64 %0, {%1, %1};" : "=l"(r) : "f"(x)); return r;
}
__device__ __forceinline__ void unpack2(ull v, float& x, float& y) {
    asm("mov.b64 {%0, %1}, %2;" : "=f"(x), "=f"(y) : "l"(v));
}
__device__ __forceinline__ ull ffma2(ull a, ull b, ull c) {
    ull d; asm("fma.rn.f32x2 %0, %1, %2, %3;" : "=l"(d) : "l"(a), "l"(b), "l"(c)); return d;
}
__device__ __forceinline__ ull fadd2(ull a, ull b) {
    ull d; asm("add.rn.f32x2 %0, %1, %2;" : "=l"(d) : "l"(a), "l"(b)); return d;
}

/* ================= K0: precompute gi tables ================= */
__global__ void k_tables(const float* __restrict__ emb,
                         const float* __restrict__ Wf, const float* __restrict__ bif, const float* __restrict__ bhf,
                         const float* __restrict__ Wb, const float* __restrict__ bib, const float* __restrict__ bhb,
                         const float* __restrict__ rW, const float* __restrict__ rb)
{
    int idx = blockIdx.x * blockDim.x + threadIdx.x;
    if (idx < 4096) {
        int dir = idx >> 11;
        int c   = (idx >> 4) & 127;
        int jj  = idx & 15;
        const float* W  = dir ? Wb : Wf;
        const float* bi = dir ? bib : bif;
        const float* bh = dir ? bhb : bhf;
        float e[16];
        #pragma unroll
        for (int d = 0; d < 16; d++) e[d] = (c == 0) ? 0.f : emb[c*16 + d];  /* padding_idx=0 */
        float v[3];
        #pragma unroll
        for (int g = 0; g < 3; g++) {
            float a = bi[g*16 + jj];
            #pragma unroll
            for (int d = 0; d < 16; d++) a += e[d] * W[(g*16 + jj)*16 + d];
            v[g] = a;
        }
        v[0] += bh[jj];        /* fold bhh for r */
        v[1] += bh[16 + jj];   /* fold bhh for z */
        int o = ((dir*128 + c)*8 + (jj >> 1))*2 + (jj & 1);
        ((float*)g_tr)[o] = v[0];
        ((float*)g_tz)[o] = v[1];
        ((float*)g_tn)[o] = v[2];
    } else if (idx < 4096 + 304) {
        int t = idx - 4096;
        int cls = t >> 4, jj = t & 15;
        int c = c_map[cls];
        float v = rb[jj];
        #pragma unroll
        for (int d = 0; d < 16; d++) v += emb[c*16 + d] * rW[jj*16 + d];
        g_ctab[t] = v;
    }
}

/* ================= K1: inv_class_emb output ================= */
__global__ void __launch_bounds__(256) k_clsemb(const int* __restrict__ ocl,
                                                const float* __restrict__ emb,
                                                float* __restrict__ out)
{
    int q = blockIdx.x * blockDim.x + threadIdx.x;   /* 0 .. NSTR*4 */
    if (q >= NSTR*4) return;
    int item = q >> 2, d4 = q & 3;
    int c = c_map[ocl[item]];
    const float4* e4 = (const float4*)emb;
    ((float4*)out)[q] = e4[c*4 + d4];
}

/* ================= K2: bidirectional GRU + fused str_emb/len =================
   8 threads per sequence; thread j owns units 2j,2j+1 (packed f32x2).
   128 thr = 16 seqs/block. grid = (3520, 2): blockIdx.y = direction.
   dir==0 blocks also emit str_emb and g_len. */
__global__ void __launch_bounds__(128, 3) k_gru(const int* __restrict__ strs,
                                                const float* __restrict__ Whf, const float* __restrict__ bhf,
                                                const float* __restrict__ Whb, const float* __restrict__ bhb,
                                                const float* __restrict__ emb,
                                                float* __restrict__ out_stremb)
{
    __shared__ ull s_tr[1024], s_tz[1024], s_tn[1024];  /* 24 KB */
    __shared__ float4 semb[520];                        /* 8.3 KB, dir0 only */
    __shared__ unsigned char sch[16*80];
    __shared__ int slen[16];
    int tid = threadIdx.x;
    int dir = blockIdx.y;
    int base = blockIdx.x * 16;

    {
        const float4* s0 = (const float4*)(g_tr + dir*1024);
        const float4* s1 = (const float4*)(g_tz + dir*1024);
        const float4* s2 = (const float4*)(g_tn + dir*1024);
        for (int i = tid; i < 512; i += 128) {
            ((float4*)s_tr)[i] = s0[i];
            ((float4*)s_tz)[i] = s1[i];
            ((float4*)s_tn)[i] = s2[i];
        }
    }
    if (dir == 0) {
        const float4* e4 = (const float4*)emb;
        for (int i = tid; i < 520; i += 128) {
            float4 v = e4[i];
            if (i < 4) v = make_float4(0.f, 0.f, 0.f, 0.f);
            semb[i] = v;
        }
    }
    const int* sp = strs + (size_t)base * 80;
    for (int i = tid; i < 1280; i += 128) sch[i] = (unsigned char)sp[i];
    __syncthreads();

    int j = tid & 7;
    int s = tid >> 3;
    unsigned gm = 0xFFu << (tid & 24);

    {   /* lengths */
        const unsigned char* ch = &sch[s*80];
        int cnt = 0;
        #pragma unroll
        for (int i = 0; i < 10; i++) cnt += (ch[j*10 + i] != 0);
        #pragma unroll
        for (int o = 4; o; o >>= 1) cnt += __shfl_xor_sync(gm, cnt, o, 8);
        if (j == 0) {
            slen[s] = cnt;
            if (dir == 0) g_len[base + s] = (unsigned char)cnt;
        }
    }
    __syncthreads();

    if (dir == 0) {   /* str_emb: 16 seqs x 320 float4, block-strided */
        float4* o4 = (float4*)out_stremb + (size_t)base * 320;
        for (int it = 0; it < 40; it++) {
            int i = it*128 + tid;
            int ss = i / 320;
            int w = i - ss*320;
            int t = w >> 2, d4 = w & 3;
            int c = (t == slen[ss]) ? EOS_TOK : (int)sch[ss*80 + t];
            o4[i] = semb[c*4 + d4];
        }
    }

    /* weights: rows 2j,2j+1 of each gate, packed */
    const float* Wp = dir ? Whb : Whf;
    const float* bh = dir ? bhb : bhf;
    int j2 = j * 2;
    ull wr[16], wz[16], wn[16];
    #pragma unroll
    for (int k = 0; k < 16; k++) {
        wr[k] = pack2(Wp[j2*16 + k],        Wp[(j2+1)*16 + k]);
        wz[k] = pack2(Wp[(16+j2)*16 + k],   Wp[(17+j2)*16 + k]);
        wn[k] = pack2(Wp[(32+j2)*16 + k],   Wp[(33+j2)*16 + k]);
    }
    ull bhn2 = pack2(bh[32 + j2], bh[33 + j2]);

    int len = slen[s];
    const unsigned char* ch = &sch[s*80];
    float h0 = 0.f, h1 = 0.f;
    int pos = dir ? (len - 1) : 0;
    int dstep = dir ? -1 : 1;
    for (int t = 0; t < len; t++, pos += dstep) {
        int c = ch[pos];
        ull ar  = s_tr[c*8 + j];     /* init with gi_r + bih_r + bhh_r */
        ull az  = s_tz[c*8 + j];
        ull gn  = s_tn[c*8 + j];
        ull ar1 = 0, az1 = 0, an0 = bhn2, an1 = 0;
        #pragma unroll
        for (int kk = 0; kk < 8; kk++) {
            float hx = __shfl_sync(gm, h0, kk, 8);
            float hy = __shfl_sync(gm, h1, kk, 8);
            ull d0 = dup2(hx), d1 = dup2(hy);
            ar  = ffma2(wr[2*kk],   d0, ar);
            ar1 = ffma2(wr[2*kk+1], d1, ar1);
            az  = ffma2(wz[2*kk],   d0, az);
            az1 = ffma2(wz[2*kk+1], d1, az1);
            an0 = ffma2(wn[2*kk],   d0, an0);
            an1 = ffma2(wn[2*kk+1], d1, an1);
        }
        ar = fadd2(ar, ar1); az = fadd2(az, az1); an0 = fadd2(an0, an1);
        float srx, sry, szx, szy, ahx, ahy, gnx, gny;
        unpack2(ar, srx, sry); unpack2(az, szx, szy);
        unpack2(an0, ahx, ahy); unpack2(gn, gnx, gny);
        float r0 = fsig(srx), r1 = fsig(sry);
        float z0 = fsig(szx), z1 = fsig(szy);
        float n0 = ftanh_(fmaf(r0, ahx, gnx));
        float n1 = ftanh_(fmaf(r1, ahy, gny));
        h0 = n0 + z0*(h0 - n0);
        h1 = n1 + z1*(h1 - n1);
    }
    ((float2*)g_hbuf)[((size_t)dir*NSTR + base + s)*8 + j] = make_float2(h0, h1);
}

/* ================= K3: class-branch vanilla RNN ================= */
__global__ void __launch_bounds__(512) k_cls(const int* __restrict__ ocl,
                                             const float* __restrict__ Whh,
                                             const float* __restrict__ bhh)
{
    __shared__ float sct[19*16];
    __shared__ unsigned char soc[32*55];
    int tid = threadIdx.x;
    if (tid < 304) sct[tid] = g_ctab[tid];
    int base = blockIdx.x * 32;
    for (int i = tid; i < 1760; i += 512) soc[i] = (unsigned char)ocl[base*55 + i];

    int j = tid & 15;
    float w[16];
    const float4* W4 = (const float4*)Whh;
    #pragma unroll
    for (int kk = 0; kk < 4; kk++) {
        float4 a = W4[j*4 + kk];
        w[kk*4+0]=a.x; w[kk*4+1]=a.y; w[kk*4+2]=a.z; w[kk*4+3]=a.w;
    }
    float bhv = bhh[j];
    __syncthreads();

    int s = tid >> 4;
    unsigned gmask = (tid & 16) ? 0xFFFF0000u : 0x0000FFFFu;
    const unsigned char* oc = &soc[s * 55];
    int cnt = 0;
    #pragma unroll
    for (int i = 0; i < 4; i++) { int p = j + 16*i; cnt += (p < 55) ? (oc[p] != 18) : 0; }
    #pragma unroll
    for (int o = 8; o; o >>= 1) cnt += __shfl_xor_sync(gmask, cnt, o, 16);
    int len = cnt;

    float h = 0.f;
    for (int t = 0; t < len; t++) {
        int c = oc[t];
        float acc = sct[c*16 + j] + bhv;
        #pragma unroll
        for (int k = 0; k < 16; k++) {
            float hk = __shfl_sync(gmask, h, k, 16);
            acc += w[k]*hk;
        }
        h = ftanh_(acc);
    }
    g_hcls[(base + s)*16 + j] = h;
}

/* ================= K4: pooling + fusion MLP ================= */
__global__ void __launch_bounds__(256) k_fuse(const float* __restrict__ W1, const float* __restrict__ b1,
                                              const float* __restrict__ W2, const float* __restrict__ b2,
                                              float* __restrict__ out)
{
    __shared__ float comb[8][48];
    __shared__ float h1s[8][16];
    int w = threadIdx.x >> 5, lane = threadIdx.x & 31;
    int b = blockIdx.x * 8 + w;
    const float* hf = &g_hbuf[0];
    const float* hb = &g_hbuf[(size_t)NSTR * 16];
    float pooled = 0.f, cnt = 0.f;
    int nb = b * ITEMS;
    for (int i = 0; i < ITEMS; i++) {
        int n = nb + i;
        if (g_len[n]) {
            cnt += 1.f;
            float hv = (lane < 16) ? hf[n*16 + lane] : hb[n*16 + (lane - 16)];
            pooled += hv;
        }
    }
    pooled = pooled / (cnt + 1e-8f);
    if (lane < 16) comb[w][lane] = g_hcls[b*16 + lane];
    comb[w][16 + lane] = pooled;
    __syncwarp();
    if (lane < 16) {
        float a = b1[lane];
        #pragma unroll
        for (int k = 0; k < 48; k++) a += W1[lane*48 + k] * comb[w][k];
        h1s[w][lane] = fmaxf(a, 0.f);
    }
    __syncwarp();
    if (lane < 24) {
        float o = b2[lane];
        #pragma unroll
        for (int k = 0; k < 16; k++) o += W2[lane*16 + k] * h1s[w][k];
        out[b*24 + lane] = o;
    }
}

extern "C" void kernel_launch(void* const* d_in, const int* in_sizes, int n_in,
                              void* d_out, int out_size)
{
    const int*   ocl  = (const int*)d_in[0];
    const int*   strs = (const int*)d_in[1];
    const float* emb  = (const float*)d_in[2];
    const float* rW   = (const float*)d_in[3];
    const float* rWhh = (const float*)d_in[4];
    const float* rbih = (const float*)d_in[5];
    const float* rbhh = (const float*)d_in[6];
    const float* gWf  = (const float*)d_in[7];
    const float* gWhf = (const float*)d_in[8];
    const float* gbif = (const float*)d_in[9];
    const float* gbhf = (const float*)d_in[10];
    const float* gWb  = (const float*)d_in[11];
    const float* gWhb = (const float*)d_in[12];
    const float* gbib = (const float*)d_in[13];
    const float* gbhb = (const float*)d_in[14];
    const float* W1   = (const float*)d_in[15];
    const float* b1   = (const float*)d_in[16];
    const float* W2   = (const float*)d_in[17];
    const float* b2   = (const float*)d_in[18];
    float* out = (float*)d_out;

    k_tables<<<18, 256>>>(emb, gWf, gbif, gbhf, gWb, gbib, gbhb, rW, rbih);
    k_clsemb<<<880, 256>>>(ocl, emb, out + OFF_CLSEMB);
    dim3 gg(3520, 2);
    k_gru<<<gg, 128>>>(strs, gWhf, gbhf, gWhb, gbhb, emb, out + OFF_STREMB);
    k_cls<<<32, 512>>>(ocl, rWhh, rbhh);
    k_fuse<<<128, 256>>>(W1, b1, W2, b2, out);
}